// round 3
// baseline (speedup 1.0000x reference)
#include <cuda_runtime.h>
#include <cuda_bf16.h>

// out[row, k] = clips[row, k - idx] for k >= idx else 0, idx = int(x[row]*N).
// rows = B*C = 1024, N = 32768, fp32. Streaming-bandwidth kernel.
//
// R3: block-uniform classification (idx is per-row constant):
//   - all-zero block  -> store zeros
//   - fully-valid     -> branch-free: load ALL chunks into regs, THEN store
//                        (forces ptxas to front-batch LDGs -> high MLP)
//   - boundary block  -> guarded scalar fallback (~1 block per row)

#define BLOCK   256
#define UNROLL  8
#define SEG     (BLOCK * 4 * UNROLL)   // 8192 floats per block

__device__ __forceinline__ float4 ld128(const float* p) {
    return *reinterpret_cast<const float4*>(p);
}

__global__ void __launch_bounds__(BLOCK)
RollScheduler_63273458204913_kernel(
    const float* __restrict__ x,
    const float* __restrict__ clips,
    float* __restrict__ out,
    int n)
{
    const int row = blockIdx.y;
    // Match jnp: (x * n).astype(int32) — f32 multiply, truncate toward zero.
    const int idx = (int)(x[row] * (float)n);

    const float* __restrict__ src = clips + (size_t)row * (size_t)n;
    float*       __restrict__ dst = out   + (size_t)row * (size_t)n;

    const int k0   = blockIdx.x * SEG;          // block segment start
    const int kT   = k0 + threadIdx.x * 4;      // this thread's first chunk
    const int r    = (4 - (idx & 3)) & 3;       // (k - idx) & 3 for k%4==0

    // ---- all-zero block: every element index < idx ----
    if (k0 + SEG <= idx) {
        const float4 z = make_float4(0.f, 0.f, 0.f, 0.f);
        #pragma unroll
        for (int u = 0; u < UNROLL; u++)
            *reinterpret_cast<float4*>(dst + kT + u * (BLOCK * 4)) = z;
        return;
    }

    // ---- fully-valid fast path? (block-uniform) ----
    // min aligned load addr: k0 - idx - r >= 0
    // max load end:          (k0 + SEG - 4) - idx - r + 8 <= n   (r>0 case;
    //                        r==0 case max is k0+SEG-idx <= n, always true)
    const bool fast = (k0 - idx - r >= 0) &&
                      (r == 0 || (k0 + SEG + 4 - idx - r) <= n);

    if (fast) {
        if (r == 0) {
            const float* s = src + (kT - idx);
            float4 v[UNROLL];
            #pragma unroll
            for (int u = 0; u < UNROLL; u++)
                v[u] = ld128(s + u * (BLOCK * 4));
            #pragma unroll
            for (int u = 0; u < UNROLL; u++)
                *reinterpret_cast<float4*>(dst + kT + u * (BLOCK * 4)) = v[u];
        } else {
            const float* s = src + (kT - idx - r);   // 16B-aligned
            float4 lo[UNROLL], hi[UNROLL];
            #pragma unroll
            for (int u = 0; u < UNROLL; u++) {
                lo[u] = ld128(s + u * (BLOCK * 4));
                hi[u] = ld128(s + u * (BLOCK * 4) + 4);
            }
            #pragma unroll
            for (int u = 0; u < UNROLL; u++) {
                float4 v;
                if (r == 1)      v = make_float4(lo[u].y, lo[u].z, lo[u].w, hi[u].x);
                else if (r == 2) v = make_float4(lo[u].z, lo[u].w, hi[u].x, hi[u].y);
                else             v = make_float4(lo[u].w, hi[u].x, hi[u].y, hi[u].z);
                *reinterpret_cast<float4*>(dst + kT + u * (BLOCK * 4)) = v;
            }
        }
        return;
    }

    // ---- boundary / edge block: guarded scalar (rare) ----
    #pragma unroll
    for (int u = 0; u < UNROLL; u++) {
        const int k = kT + u * (BLOCK * 4);
        if (k >= n) break;
        const int base = k - idx;   // base+3 <= n-1 always (idx >= 0)
        float4 v;
        v.x = (base     >= 0) ? src[base]     : 0.0f;
        v.y = (base + 1 >= 0) ? src[base + 1] : 0.0f;
        v.z = (base + 2 >= 0) ? src[base + 2] : 0.0f;
        v.w = (base + 3 >= 0) ? src[base + 3] : 0.0f;
        *reinterpret_cast<float4*>(dst + k) = v;
    }
}

extern "C" void kernel_launch(void* const* d_in, const int* in_sizes, int n_in,
                              void* d_out, int out_size) {
    const float* x     = (const float*)d_in[0];   // (B, C)
    const float* clips = (const float*)d_in[1];   // (B, C, N)
    // d_in[2] = actual — unused in the forward computation.
    float* out = (float*)d_out;

    const int rows = in_sizes[0];                 // B*C = 1024
    const int n    = in_sizes[1] / in_sizes[0];   // N = 32768

    dim3 block(BLOCK);
    dim3 grid((n + SEG - 1) / SEG, rows);
    RollScheduler_63273458204913_kernel<<<grid, block>>>(x, clips, out, n);
}

// round 4
// speedup vs baseline: 1.1751x; 1.1751x over previous
#include <cuda_runtime.h>
#include <cuda_bf16.h>

// out[row, k] = clips[row, k - idx] for k >= idx else 0, idx = int(x[row]*N).
// rows = B*C = 1024, N = 32768, fp32. Streaming-bandwidth kernel.
//
// R4: UNROLL=4 batched loads -> regs ~48 so 4 blocks/SM (32 warps, 100%
// theoretical occ) while keeping per-warp MLP=4..8 (SM-wide MLP ~128).
// Streaming cache hints (__ldcs/__stcs): both streams are touch-once.
// Block-uniform classification retained (idx constant per row).

#define BLOCK   256
#define UNROLL  4
#define SEG     (BLOCK * 4 * UNROLL)   // 4096 floats per block

__device__ __forceinline__ float4 ldcs4(const float* p) {
    return __ldcs(reinterpret_cast<const float4*>(p));
}
__device__ __forceinline__ void stcs4(float* p, float4 v) {
    __stcs(reinterpret_cast<float4*>(p), v);
}

__global__ void __launch_bounds__(BLOCK, 4)
RollScheduler_63273458204913_kernel(
    const float* __restrict__ x,
    const float* __restrict__ clips,
    float* __restrict__ out,
    int n)
{
    const int row = blockIdx.y;
    // Match jnp: (x * n).astype(int32) — f32 multiply, truncate toward zero.
    const int idx = (int)(x[row] * (float)n);

    const float* __restrict__ src = clips + (size_t)row * (size_t)n;
    float*       __restrict__ dst = out   + (size_t)row * (size_t)n;

    const int k0 = blockIdx.x * SEG;          // block segment start
    const int kT = k0 + threadIdx.x * 4;      // this thread's first chunk
    const int r  = (4 - (idx & 3)) & 3;       // (k - idx) & 3 for k%4==0

    // ---- all-zero block ----
    if (k0 + SEG <= idx) {
        const float4 z = make_float4(0.f, 0.f, 0.f, 0.f);
        #pragma unroll
        for (int u = 0; u < UNROLL; u++)
            stcs4(dst + kT + u * (BLOCK * 4), z);
        return;
    }

    // ---- fully-valid fast path? (block-uniform) ----
    const bool fast = (k0 - idx - r >= 0) &&
                      (r == 0 || (k0 + SEG + 4 - idx - r) <= n);

    if (fast) {
        if (r == 0) {
            const float* s = src + (kT - idx);
            float4 v[UNROLL];
            #pragma unroll
            for (int u = 0; u < UNROLL; u++)
                v[u] = ldcs4(s + u * (BLOCK * 4));
            #pragma unroll
            for (int u = 0; u < UNROLL; u++)
                stcs4(dst + kT + u * (BLOCK * 4), v[u]);
        } else {
            const float* s = src + (kT - idx - r);   // 16B-aligned
            float4 lo[UNROLL], hi[UNROLL];
            #pragma unroll
            for (int u = 0; u < UNROLL; u++) {
                lo[u] = ldcs4(s + u * (BLOCK * 4));
                hi[u] = ldcs4(s + u * (BLOCK * 4) + 4);
            }
            #pragma unroll
            for (int u = 0; u < UNROLL; u++) {
                float4 v;
                if (r == 1)      v = make_float4(lo[u].y, lo[u].z, lo[u].w, hi[u].x);
                else if (r == 2) v = make_float4(lo[u].z, lo[u].w, hi[u].x, hi[u].y);
                else             v = make_float4(lo[u].w, hi[u].x, hi[u].y, hi[u].z);
                stcs4(dst + kT + u * (BLOCK * 4), v);
            }
        }
        return;
    }

    // ---- boundary / edge block: guarded scalar (rare, ~1 block per row) ----
    #pragma unroll
    for (int u = 0; u < UNROLL; u++) {
        const int k = kT + u * (BLOCK * 4);
        if (k >= n) break;
        const int base = k - idx;   // base+3 <= n-1 always (idx >= 0)
        float4 v;
        v.x = (base     >= 0) ? src[base]     : 0.0f;
        v.y = (base + 1 >= 0) ? src[base + 1] : 0.0f;
        v.z = (base + 2 >= 0) ? src[base + 2] : 0.0f;
        v.w = (base + 3 >= 0) ? src[base + 3] : 0.0f;
        stcs4(dst + k, v);
    }
}

extern "C" void kernel_launch(void* const* d_in, const int* in_sizes, int n_in,
                              void* d_out, int out_size) {
    const float* x     = (const float*)d_in[0];   // (B, C)
    const float* clips = (const float*)d_in[1];   // (B, C, N)
    // d_in[2] = actual — unused in the forward computation.
    float* out = (float*)d_out;

    const int rows = in_sizes[0];                 // B*C = 1024
    const int n    = in_sizes[1] / in_sizes[0];   // N = 32768

    dim3 block(BLOCK);
    dim3 grid((n + SEG - 1) / SEG, rows);
    RollScheduler_63273458204913_kernel<<<grid, block>>>(x, clips, out, n);
}